// round 1
// baseline (speedup 1.0000x reference)
#include <cuda_runtime.h>
#include <math.h>
#include <float.h>

#define CC 256
#define HWSZ 4096
#define BATCH 4
#define NHEAD 4
#define DHEAD 64
#define NGROUPS 8

// -------- scratch (device globals; no allocations allowed) --------
__device__ float g_h[(size_t)BATCH * CC * HWSZ];          // normalized input
__device__ float g_qkv[(size_t)BATCH * 3 * CC * HWSZ];    // q (pre-scaled), k, v
__device__ float g_o[(size_t)BATCH * CC * HWSZ];          // attention output

// ============================================================
// GroupNorm: one block per (batch, group). 32 ch * 4096 = 131072 contiguous floats.
// ============================================================
__global__ void groupnorm_kernel(const float* __restrict__ x,
                                 const float* __restrict__ w,
                                 const float* __restrict__ b) {
    const int CH = CC / NGROUPS;          // 32
    const int NEL = CH * HWSZ;            // 131072
    int bg = blockIdx.x;
    int bi = bg / NGROUPS, g = bg % NGROUPS;
    const float* xp = x + (size_t)bi * CC * HWSZ + (size_t)g * CH * HWSZ;
    float* hp = g_h + (size_t)bi * CC * HWSZ + (size_t)g * CH * HWSZ;
    int tid = threadIdx.x;

    float s = 0.f, ss = 0.f;
    for (int i = tid * 4; i < NEL; i += blockDim.x * 4) {
        float4 v = *(const float4*)(xp + i);
        s  += v.x + v.y + v.z + v.w;
        ss += v.x * v.x + v.y * v.y + v.z * v.z + v.w * v.w;
    }
    __shared__ float rs[256], rss[256];
    rs[tid] = s; rss[tid] = ss;
    __syncthreads();
    for (int o = 128; o > 0; o >>= 1) {
        if (tid < o) { rs[tid] += rs[tid + o]; rss[tid] += rss[tid + o]; }
        __syncthreads();
    }
    float mean = rs[0] / (float)NEL;
    float var  = rss[0] / (float)NEL - mean * mean;
    float rstd = rsqrtf(var + 1e-5f);

    for (int i = tid * 4; i < NEL; i += blockDim.x * 4) {
        int c = g * CH + (i >> 12);
        float sc  = rstd * w[c];
        float off = b[c] - mean * sc;
        float4 v = *(const float4*)(xp + i);
        float4 o4;
        o4.x = v.x * sc + off;
        o4.y = v.y * sc + off;
        o4.z = v.z * sc + off;
        o4.w = v.w * sc + off;
        *(float4*)(hp + i) = o4;
    }
}

// ============================================================
// SGEMM: out[b] = A[M,K] @ Bm[b][K,HW] + bias (+resid). BM=128,BN=64,BK=16.
// 256 threads, 8x4 register tile. QKV mode scales q rows by d^-0.5.
// ============================================================
template<int M_TOTAL, bool QKV_MODE>
__global__ void gemm_kernel(const float* __restrict__ A,
                            const float* __restrict__ Bm,
                            const float* __restrict__ bias,
                            const float* __restrict__ resid,
                            float* __restrict__ out) {
    const int K = 256, BM = 128, BN = 64, BK = 16;
    int bb = blockIdx.z;
    int m0 = blockIdx.y * BM;
    int n0 = blockIdx.x * BN;
    const float* Bp = Bm + (size_t)bb * K * HWSZ;
    float* outp = out + (size_t)bb * M_TOTAL * HWSZ;

    __shared__ float a_s[BK][BM];
    __shared__ float b_s[BK][BN];

    int tid = threadIdx.x;
    int ty = tid >> 4, tx = tid & 15;

    float acc[8][4];
    #pragma unroll
    for (int r = 0; r < 8; r++)
        #pragma unroll
        for (int c = 0; c < 4; c++) acc[r][c] = 0.f;

    for (int k0 = 0; k0 < K; k0 += BK) {
        // A tile: 128 rows x 16 k (transpose into a_s[k][row])
        #pragma unroll
        for (int e = tid; e < BM * BK / 4; e += 256) {
            int row = e >> 2, kq = e & 3;
            float4 v = *(const float4*)(A + (size_t)(m0 + row) * K + k0 + kq * 4);
            a_s[kq * 4 + 0][row] = v.x;
            a_s[kq * 4 + 1][row] = v.y;
            a_s[kq * 4 + 2][row] = v.z;
            a_s[kq * 4 + 3][row] = v.w;
        }
        // B tile: 16 x 64
        {
            int kk = tid >> 4, n4 = tid & 15;
            *(float4*)&b_s[kk][n4 * 4] =
                *(const float4*)(Bp + (size_t)(k0 + kk) * HWSZ + n0 + n4 * 4);
        }
        __syncthreads();
        #pragma unroll
        for (int k = 0; k < BK; k++) {
            float af[8], bf[4];
            *(float4*)&af[0] = *(float4*)&a_s[k][ty * 8];
            *(float4*)&af[4] = *(float4*)&a_s[k][ty * 8 + 4];
            *(float4*)&bf[0] = *(float4*)&b_s[k][tx * 4];
            #pragma unroll
            for (int r = 0; r < 8; r++)
                #pragma unroll
                for (int c = 0; c < 4; c++)
                    acc[r][c] += af[r] * bf[c];
        }
        __syncthreads();
    }

    #pragma unroll
    for (int r = 0; r < 8; r++) {
        int o = m0 + ty * 8 + r;
        float bv = bias[o];
        float4 v;
        v.x = acc[r][0] + bv;
        v.y = acc[r][1] + bv;
        v.z = acc[r][2] + bv;
        v.w = acc[r][3] + bv;
        if (QKV_MODE) {
            if (o < CC) { v.x *= 0.125f; v.y *= 0.125f; v.z *= 0.125f; v.w *= 0.125f; }
        } else {
            float4 rv = *(const float4*)(resid + ((size_t)bb * M_TOTAL + o) * HWSZ + n0 + tx * 4);
            v.x += rv.x; v.y += rv.y; v.z += rv.z; v.w += rv.w;
        }
        *(float4*)(outp + (size_t)o * HWSZ + n0 + tx * 4) = v;
    }
}

// ============================================================
// Fused attention (flash-style), per (b,h). Q tile BM=128 rows, key tiles BN=64.
// Layouts: q/k/v are [d, HW] per head. S computed as Q^T K via smem.
// ============================================================
__global__ void attn_kernel() {
    const int BM = 128, BN = 64, D = 64;
    extern __shared__ float sm[];
    float* q_s  = sm;                      // [D][BM]
    float* k_s  = q_s + D * BM;            // [D][BN]
    float* v_s  = k_s + D * BN;            // [BN][68]  (transposed: [j][c], pad)
    float* p_s  = v_s + BN * 68;           // [BN][132] (transposed: [j][i], pad)
    float* m_s  = p_s + BN * 132;          // [BM]
    float* l_s  = m_s + BM;                // [BM]
    float* al_s = l_s + BM;                // [BM]

    int i0 = blockIdx.x * BM;
    int bh = blockIdx.y;
    int bb = bh / NHEAD, hh = bh % NHEAD;
    const float* qg = g_qkv + ((size_t)bb * 3 * CC +          hh * DHEAD) * HWSZ;
    const float* kg = g_qkv + ((size_t)bb * 3 * CC +  CC +    hh * DHEAD) * HWSZ;
    const float* vg = g_qkv + ((size_t)bb * 3 * CC + 2 * CC + hh * DHEAD) * HWSZ;
    float* og = g_o + ((size_t)bb * CC + hh * DHEAD) * HWSZ;

    int tid = threadIdx.x;
    int ty = tid >> 4, tx = tid & 15;

    // load Q tile [D][BM]
    #pragma unroll
    for (int e = tid; e < D * BM / 4; e += 256) {
        int c = e >> 5, f = e & 31;
        *(float4*)&q_s[c * BM + f * 4] = *(const float4*)(qg + (size_t)c * HWSZ + i0 + f * 4);
    }
    if (tid < BM) { m_s[tid] = -FLT_MAX; l_s[tid] = 0.f; }

    float o_acc[8][4];
    #pragma unroll
    for (int r = 0; r < 8; r++)
        #pragma unroll
        for (int c = 0; c < 4; c++) o_acc[r][c] = 0.f;

    for (int j0 = 0; j0 < HWSZ; j0 += BN) {
        __syncthreads();   // prior iter done with k_s/v_s/p_s
        // K tile [D][BN]
        #pragma unroll
        for (int e = tid; e < D * BN / 4; e += 256) {
            int c = e >> 4, f = e & 15;
            *(float4*)&k_s[c * BN + f * 4] = *(const float4*)(kg + (size_t)c * HWSZ + j0 + f * 4);
        }
        // V tile transposed -> v_s[j][c]
        #pragma unroll
        for (int e = tid; e < D * BN / 4; e += 256) {
            int c = e >> 4, f = e & 15;
            float4 v = *(const float4*)(vg + (size_t)c * HWSZ + j0 + f * 4);
            v_s[(f * 4 + 0) * 68 + c] = v.x;
            v_s[(f * 4 + 1) * 68 + c] = v.y;
            v_s[(f * 4 + 2) * 68 + c] = v.z;
            v_s[(f * 4 + 3) * 68 + c] = v.w;
        }
        __syncthreads();

        // S = Q^T K  (rows i = ty*8.., cols j = tx*4..)
        float s[8][4];
        #pragma unroll
        for (int r = 0; r < 8; r++)
            #pragma unroll
            for (int c = 0; c < 4; c++) s[r][c] = 0.f;
        #pragma unroll 8
        for (int c = 0; c < D; c++) {
            float qa[8], kb[4];
            *(float4*)&qa[0] = *(float4*)&q_s[c * BM + ty * 8];
            *(float4*)&qa[4] = *(float4*)&q_s[c * BM + ty * 8 + 4];
            *(float4*)&kb[0] = *(float4*)&k_s[c * BN + tx * 4];
            #pragma unroll
            for (int r = 0; r < 8; r++)
                #pragma unroll
                for (int cc = 0; cc < 4; cc++)
                    s[r][cc] += qa[r] * kb[cc];
        }
        // write S^T into p_s[j][i] (vectorized over i)
        #pragma unroll
        for (int cc = 0; cc < 4; cc++) {
            float4 v0 = make_float4(s[0][cc], s[1][cc], s[2][cc], s[3][cc]);
            float4 v1 = make_float4(s[4][cc], s[5][cc], s[6][cc], s[7][cc]);
            *(float4*)&p_s[(tx * 4 + cc) * 132 + ty * 8]     = v0;
            *(float4*)&p_s[(tx * 4 + cc) * 132 + ty * 8 + 4] = v1;
        }
        __syncthreads();

        // online softmax: 2 threads per row, 32 cols each
        {
            int i = tid >> 1, hf = tid & 1;
            float vals[32];
            float mx = -FLT_MAX;
            #pragma unroll
            for (int j = 0; j < 32; j++) {
                vals[j] = p_s[(hf * 32 + j) * 132 + i];
                mx = fmaxf(mx, vals[j]);
            }
            mx = fmaxf(mx, __shfl_xor_sync(0xffffffffu, mx, 1));
            float mo = m_s[i];
            float mn = fmaxf(mo, mx);
            float lsum = 0.f;
            #pragma unroll
            for (int j = 0; j < 32; j++) {
                float p = __expf(vals[j] - mn);
                lsum += p;
                p_s[(hf * 32 + j) * 132 + i] = p;
            }
            lsum += __shfl_xor_sync(0xffffffffu, lsum, 1);
            if (hf == 0) {
                float a = __expf(mo - mn);
                al_s[i] = a;
                m_s[i] = mn;
                l_s[i] = l_s[i] * a + lsum;
            }
        }
        __syncthreads();

        // O = O*alpha + P @ V^T  (O rows i = ty*8.., cols c = tx*4..)
        #pragma unroll
        for (int r = 0; r < 8; r++) {
            float a = al_s[ty * 8 + r];
            #pragma unroll
            for (int cc = 0; cc < 4; cc++) o_acc[r][cc] *= a;
        }
        #pragma unroll 8
        for (int j = 0; j < BN; j++) {
            float pa[8], vb[4];
            *(float4*)&pa[0] = *(float4*)&p_s[j * 132 + ty * 8];
            *(float4*)&pa[4] = *(float4*)&p_s[j * 132 + ty * 8 + 4];
            *(float4*)&vb[0] = *(float4*)&v_s[j * 68 + tx * 4];
            #pragma unroll
            for (int r = 0; r < 8; r++)
                #pragma unroll
                for (int cc = 0; cc < 4; cc++)
                    o_acc[r][cc] += pa[r] * vb[cc];
        }
    }
    __syncthreads();   // everyone done reading p_s/v_s

    // divide by l, stage O^T into p_s[c][i], then coalesced store
    #pragma unroll
    for (int r = 0; r < 8; r++) {
        float inv = 1.f / l_s[ty * 8 + r];
        #pragma unroll
        for (int cc = 0; cc < 4; cc++)
            p_s[(tx * 4 + cc) * 132 + ty * 8 + r] = o_acc[r][cc] * inv;
    }
    __syncthreads();
    #pragma unroll
    for (int e = tid; e < D * BM / 4; e += 256) {
        int c = e >> 5, f = e & 31;
        float4 v = *(float4*)&p_s[c * 132 + f * 4];
        *(float4*)(og + (size_t)c * HWSZ + i0 + f * 4) = v;
    }
}

// ============================================================
extern "C" void kernel_launch(void* const* d_in, const int* in_sizes, int n_in,
                              void* d_out, int out_size) {
    const float* x      = (const float*)d_in[0];
    const float* norm_w = (const float*)d_in[1];
    const float* norm_b = (const float*)d_in[2];
    const float* qkv_w  = (const float*)d_in[3];
    const float* qkv_b  = (const float*)d_in[4];
    const float* proj_w = (const float*)d_in[5];
    const float* proj_b = (const float*)d_in[6];
    float* out = (float*)d_out;

    void *ph, *pqkv, *po;
    cudaGetSymbolAddress(&ph,   g_h);
    cudaGetSymbolAddress(&pqkv, g_qkv);
    cudaGetSymbolAddress(&po,   g_o);

    const int ATTN_SMEM = (64 * 128 + 64 * 64 + 64 * 68 + 64 * 132 + 3 * 128) * 4;
    cudaFuncSetAttribute(attn_kernel, cudaFuncAttributeMaxDynamicSharedMemorySize, ATTN_SMEM);

    groupnorm_kernel<<<BATCH * NGROUPS, 256>>>(x, norm_w, norm_b);

    gemm_kernel<768, true><<<dim3(HWSZ / 64, 768 / 128, BATCH), 256>>>(
        qkv_w, (const float*)ph, qkv_b, nullptr, (float*)pqkv);

    attn_kernel<<<dim3(HWSZ / 128, BATCH * NHEAD), 256, ATTN_SMEM>>>();

    gemm_kernel<256, false><<<dim3(HWSZ / 64, 256 / 128, BATCH), 256>>>(
        proj_w, (const float*)po, proj_b, x, out);
}

// round 4
// speedup vs baseline: 2.9362x; 2.9362x over previous
#include <cuda_runtime.h>
#include <math.h>
#include <stdint.h>

#define CC 256
#define HWSZ 4096
#define BATCH 4
#define NHEAD 4
#define NGROUPS 8
#define NBH 16

// -------- scratch (device globals; no allocations allowed) --------
__device__ float g_h  [(size_t)BATCH * CC * HWSZ];        // normalized input
__device__ float g_qkv[(size_t)BATCH * 3 * CC * HWSZ];    // v lives in last third: [b][512 + h*64 + c][token]
__device__ float g_qt [(size_t)NBH * HWSZ * 64];          // q: [bh][token][c], *0.125*log2e, tf32-rounded
__device__ float g_kt [(size_t)NBH * HWSZ * 64];          // k: [bh][token][c], tf32-rounded
__device__ float g_o  [(size_t)BATCH * CC * HWSZ];        // attention out [b][c][token]

// ============================================================
// helpers (sm_80-baseline PTX only — no 'a'-suffix features!)
// ============================================================
__device__ __forceinline__ uint32_t smem_u32(const void* p) {
    uint32_t a;
    asm("{ .reg .u64 t; cvta.to.shared.u64 t, %1; cvt.u32.u64 %0, t; }" : "=r"(a) : "l"(p));
    return a;
}
__device__ __forceinline__ float tf32r(float x) {
    uint32_t u;
    asm("cvt.rna.tf32.f32 %0, %1;" : "=r"(u) : "f"(x));
    return __uint_as_float(u);
}
__device__ __forceinline__ float ex2f(float x) {
    float r;
    asm("ex2.approx.ftz.f32 %0, %1;" : "=f"(r) : "f"(x));
    return r;
}
__device__ __forceinline__ void cp16(uint32_t dst, const void* src) {
    asm volatile("cp.async.cg.shared.global [%0], [%1], 16;" :: "r"(dst), "l"(src) : "memory");
}
#define CP_COMMIT()  asm volatile("cp.async.commit_group;" ::: "memory")
#define CP_WAIT0()   asm volatile("cp.async.wait_group 0;" ::: "memory")

// m16n8k8 tf32 mma: A row-major (4 regs), B col-major (2 regs), C/D f32 (4 regs)
__device__ __forceinline__ void mma8(float c[4], const float a_[4], uint32_t b0, uint32_t b1) {
    asm volatile("mma.sync.aligned.m16n8k8.row.col.f32.tf32.tf32.f32 "
        "{%0,%1,%2,%3}, {%4,%5,%6,%7}, {%8,%9}, {%0,%1,%2,%3};"
        : "+f"(c[0]), "+f"(c[1]), "+f"(c[2]), "+f"(c[3])
        : "r"(__float_as_uint(a_[0])), "r"(__float_as_uint(a_[1])),
          "r"(__float_as_uint(a_[2])), "r"(__float_as_uint(a_[3])),
          "r"(b0), "r"(b1));
}

// ============================================================
// GroupNorm
// ============================================================
__global__ void groupnorm_kernel(const float* __restrict__ x,
                                 const float* __restrict__ w,
                                 const float* __restrict__ b) {
    const int CH = CC / NGROUPS;
    const int NEL = CH * HWSZ;
    int bg = blockIdx.x;
    int bi = bg / NGROUPS, g = bg % NGROUPS;
    const float* xp = x + (size_t)bi * CC * HWSZ + (size_t)g * CH * HWSZ;
    float* hp = g_h + (size_t)bi * CC * HWSZ + (size_t)g * CH * HWSZ;
    int tid = threadIdx.x;

    float s = 0.f, ss = 0.f;
    for (int i = tid * 4; i < NEL; i += blockDim.x * 4) {
        float4 v = *(const float4*)(xp + i);
        s  += v.x + v.y + v.z + v.w;
        ss += v.x * v.x + v.y * v.y + v.z * v.z + v.w * v.w;
    }
    __shared__ float rs[256], rss[256];
    rs[tid] = s; rss[tid] = ss;
    __syncthreads();
    for (int o = 128; o > 0; o >>= 1) {
        if (tid < o) { rs[tid] += rs[tid + o]; rss[tid] += rss[tid + o]; }
        __syncthreads();
    }
    float mean = rs[0] / (float)NEL;
    float var  = rss[0] / (float)NEL - mean * mean;
    float rstd = rsqrtf(var + 1e-5f);

    for (int i = tid * 4; i < NEL; i += blockDim.x * 4) {
        int c = g * CH + (i >> 12);
        float sc  = rstd * w[c];
        float off = b[c] - mean * sc;
        float4 v = *(const float4*)(xp + i);
        float4 o4;
        o4.x = v.x * sc + off;
        o4.y = v.y * sc + off;
        o4.z = v.z * sc + off;
        o4.w = v.w * sc + off;
        *(float4*)(hp + i) = o4;
    }
}

// ============================================================
// SGEMM (SIMT): out = A[M,K] @ Bm[b][K,HW] + bias (+resid).
// QKV mode: q -> g_qt (scaled+rounded, [token][c]), k -> g_kt, v -> g_qkv (rounded, [c][token]).
// ============================================================
template<int M_TOTAL, bool QKV_MODE>
__global__ void gemm_kernel(const float* __restrict__ A,
                            const float* __restrict__ Bm,
                            const float* __restrict__ bias,
                            const float* __restrict__ resid,
                            float* __restrict__ out) {
    const int K = 256, BM = 128, BN = 64, BK = 16;
    int bb = blockIdx.z;
    int m0 = blockIdx.y * BM;
    int n0 = blockIdx.x * BN;
    const float* Bp = Bm + (size_t)bb * K * HWSZ;
    float* outp = out + (size_t)bb * M_TOTAL * HWSZ;

    __shared__ float a_s[BK][BM];
    __shared__ float b_s[BK][BN];

    int tid = threadIdx.x;
    int ty = tid >> 4, tx = tid & 15;

    float acc[8][4];
    #pragma unroll
    for (int r = 0; r < 8; r++)
        #pragma unroll
        for (int c = 0; c < 4; c++) acc[r][c] = 0.f;

    for (int k0 = 0; k0 < K; k0 += BK) {
        #pragma unroll
        for (int e = tid; e < BM * BK / 4; e += 256) {
            int row = e >> 2, kq = e & 3;
            float4 v = *(const float4*)(A + (size_t)(m0 + row) * K + k0 + kq * 4);
            a_s[kq * 4 + 0][row] = v.x;
            a_s[kq * 4 + 1][row] = v.y;
            a_s[kq * 4 + 2][row] = v.z;
            a_s[kq * 4 + 3][row] = v.w;
        }
        {
            int kk = tid >> 4, n4 = tid & 15;
            *(float4*)&b_s[kk][n4 * 4] =
                *(const float4*)(Bp + (size_t)(k0 + kk) * HWSZ + n0 + n4 * 4);
        }
        __syncthreads();
        #pragma unroll
        for (int k = 0; k < BK; k++) {
            float af[8], bf[4];
            *(float4*)&af[0] = *(float4*)&a_s[k][ty * 8];
            *(float4*)&af[4] = *(float4*)&a_s[k][ty * 8 + 4];
            *(float4*)&bf[0] = *(float4*)&b_s[k][tx * 4];
            #pragma unroll
            for (int r = 0; r < 8; r++)
                #pragma unroll
                for (int c = 0; c < 4; c++)
                    acc[r][c] += af[r] * bf[c];
        }
        __syncthreads();
    }

    #pragma unroll
    for (int r = 0; r < 8; r++) {
        int o = m0 + ty * 8 + r;
        float bv = bias[o];
        float vals[4];
        #pragma unroll
        for (int c = 0; c < 4; c++) vals[c] = acc[r][c] + bv;

        if (QKV_MODE) {
            if (o < CC) {            // q: scale by d^-1/2 * log2e, round, transpose
                int bh = bb * NHEAD + (o >> 6), c8 = o & 63;
                #pragma unroll
                for (int c = 0; c < 4; c++) {
                    int tok = n0 + tx * 4 + c;
                    g_qt[((size_t)bh * HWSZ + tok) * 64 + c8] = tf32r(vals[c] * 0.18033688011112042f);
                }
            } else if (o < 2 * CC) { // k: round, transpose
                int bh = bb * NHEAD + ((o - CC) >> 6), c8 = o & 63;
                #pragma unroll
                for (int c = 0; c < 4; c++) {
                    int tok = n0 + tx * 4 + c;
                    g_kt[((size_t)bh * HWSZ + tok) * 64 + c8] = tf32r(vals[c]);
                }
            } else {                 // v: round, keep [c][token] layout
                float4 v4;
                v4.x = tf32r(vals[0]); v4.y = tf32r(vals[1]);
                v4.z = tf32r(vals[2]); v4.w = tf32r(vals[3]);
                *(float4*)(outp + (size_t)o * HWSZ + n0 + tx * 4) = v4;
            }
        } else {
            float4 rv = *(const float4*)(resid + ((size_t)bb * M_TOTAL + o) * HWSZ + n0 + tx * 4);
            float4 v4;
            v4.x = vals[0] + rv.x; v4.y = vals[1] + rv.y;
            v4.z = vals[2] + rv.z; v4.w = vals[3] + rv.w;
            *(float4*)(outp + (size_t)o * HWSZ + n0 + tx * 4) = v4;
        }
    }
}

// ============================================================
// FlashAttention-2 style tf32 mma.sync attention.
// CTA = (bh, 128-query tile); 4 warps x 32 rows; 64 key-tiles of 64.
// smem: K[2][64][68] | V[2][64][68] | P[128][68]  = 104448 B
// ============================================================
#define LDP 68
#define KVSTRIDE (64 * LDP)          // floats per K/V buffer
#define ATTN_SMEM_BYTES ((4 * KVSTRIDE + 128 * LDP) * 4)

__global__ void __launch_bounds__(128) attn_mma_kernel() {
    extern __shared__ float sm[];
    float* ks_base = sm;                     // 2 bufs [64][68]  (rows = token, cols = chan)
    float* vs_base = sm + 2 * KVSTRIDE;      // 2 bufs [64][68]  (rows = chan,  cols = token)
    float* p_s     = sm + 4 * KVSTRIDE;      // [128][68]        (rows = query, cols = key)

    const int tid = threadIdx.x, lane = tid & 31, wid = tid >> 5;
    const int g4 = lane >> 2, t4 = lane & 3;
    const int bh = blockIdx.y;
    const int bb = bh >> 2, hh = bh & 3;
    const int i0 = blockIdx.x * 128;
    const int wrow = wid * 32;

    const float* qg = g_qt + (size_t)bh * HWSZ * 64;
    const float* kg = g_kt + (size_t)bh * HWSZ * 64;
    const float* vg = g_qkv + ((size_t)bb * 768 + 512 + hh * 64) * HWSZ;

    const uint32_t ks_u = smem_u32(ks_base);
    const uint32_t vs_u = smem_u32(vs_base);

    // ---- Q fragments in registers (held for whole kernel) ----
    float qf[2][8][4];
    #pragma unroll
    for (int mt = 0; mt < 2; mt++) {
        const float* qr0 = qg + (size_t)(i0 + wrow + mt * 16 + g4) * 64;
        const float* qr1 = qr0 + 8 * 64;
        #pragma unroll
        for (int kt = 0; kt < 8; kt++) {
            qf[mt][kt][0] = qr0[kt * 8 + t4];
            qf[mt][kt][1] = qr1[kt * 8 + t4];
            qf[mt][kt][2] = qr0[kt * 8 + t4 + 4];
            qf[mt][kt][3] = qr1[kt * 8 + t4 + 4];
        }
    }

    float of[2][8][4];
    #pragma unroll
    for (int mt = 0; mt < 2; mt++)
        #pragma unroll
        for (int nt = 0; nt < 8; nt++)
            #pragma unroll
            for (int i = 0; i < 4; i++) of[mt][nt][i] = 0.f;
    float lrun[2][2] = {{0.f, 0.f}, {0.f, 0.f}};

    // ---- prologue: tile 0 into buf 0 ----
    #pragma unroll 4
    for (int e = tid; e < 1024; e += 128) {
        int r = e >> 4, c = e & 15;
        cp16(ks_u + (r * LDP + c * 4) * 4, kg + (size_t)r * 64 + c * 4);
    }
    #pragma unroll 4
    for (int e = tid; e < 1024; e += 128) {
        int r = e >> 4, c = e & 15;
        cp16(vs_u + (r * LDP + c * 4) * 4, vg + (size_t)r * HWSZ + c * 4);
    }
    CP_COMMIT();

    for (int j = 0; j < 64; j++) {
        const int buf = j & 1;
        const float* kt_s = ks_base + buf * KVSTRIDE;
        const float* vt_s = vs_base + buf * KVSTRIDE;

        CP_WAIT0();
        __syncthreads();

        // prefetch next tile into other buffer (overlaps with compute below)
        if (j < 63) {
            const uint32_t kd = ks_u + (buf ^ 1) * KVSTRIDE * 4;
            const uint32_t vd = vs_u + (buf ^ 1) * KVSTRIDE * 4;
            const float* kn = kg + (size_t)(j + 1) * 64 * 64;
            const float* vn = vg + (j + 1) * 64;
            #pragma unroll 4
            for (int e = tid; e < 1024; e += 128) {
                int r = e >> 4, c = e & 15;
                cp16(kd + (r * LDP + c * 4) * 4, kn + (size_t)r * 64 + c * 4);
            }
            #pragma unroll 4
            for (int e = tid; e < 1024; e += 128) {
                int r = e >> 4, c = e & 15;
                cp16(vd + (r * LDP + c * 4) * 4, vn + (size_t)r * HWSZ + c * 4);
            }
            CP_COMMIT();
        }

        // ---- S = Q @ K^T  (per warp: 32x64) ----
        float sf[2][8][4];
        #pragma unroll
        for (int mt = 0; mt < 2; mt++)
            #pragma unroll
            for (int nt = 0; nt < 8; nt++)
                #pragma unroll
                for (int i = 0; i < 4; i++) sf[mt][nt][i] = 0.f;

        #pragma unroll
        for (int kt = 0; kt < 8; kt++) {
            #pragma unroll
            for (int nt = 0; nt < 8; nt++) {
                uint32_t b0 = __float_as_uint(kt_s[(nt * 8 + g4) * LDP + kt * 8 + t4]);
                uint32_t b1 = __float_as_uint(kt_s[(nt * 8 + g4) * LDP + kt * 8 + t4 + 4]);
                mma8(sf[0][nt], qf[0][kt], b0, b1);
                mma8(sf[1][nt], qf[1][kt], b0, b1);
            }
        }

        // ---- softmax (max-free): P = exp2(S); accumulate row sums; store P ----
        #pragma unroll
        for (int mt = 0; mt < 2; mt++) {
            float* pr0 = p_s + (wrow + mt * 16 + g4) * LDP;
            float* pr1 = pr0 + 8 * LDP;
            #pragma unroll
            for (int nt = 0; nt < 8; nt++) {
                float p0 = tf32r(ex2f(sf[mt][nt][0]));
                float p1 = tf32r(ex2f(sf[mt][nt][1]));
                float p2 = tf32r(ex2f(sf[mt][nt][2]));
                float p3 = tf32r(ex2f(sf[mt][nt][3]));
                lrun[mt][0] += p0 + p1;
                lrun[mt][1] += p2 + p3;
                *(float2*)(pr0 + nt * 8 + 2 * t4) = make_float2(p0, p1);
                *(float2*)(pr1 + nt * 8 + 2 * t4) = make_float2(p2, p3);
            }
        }
        __syncwarp();   // P rows are warp-private: warp-level exchange only

        // ---- O += P @ V^T  (A = P from smem, B = V) ----
        #pragma unroll
        for (int kt = 0; kt < 8; kt++) {
            float a[2][4];
            #pragma unroll
            for (int mt = 0; mt < 2; mt++) {
                const float* pr = p_s + (wrow + mt * 16 + g4) * LDP + kt * 8;
                a[mt][0] = pr[t4];
                a[mt][1] = pr[8 * LDP + t4];
                a[mt][2] = pr[t4 + 4];
                a[mt][3] = pr[8 * LDP + t4 + 4];
            }
            #pragma unroll
            for (int nt = 0; nt < 8; nt++) {
                uint32_t b0 = __float_as_uint(vt_s[(nt * 8 + g4) * LDP + kt * 8 + t4]);
                uint32_t b1 = __float_as_uint(vt_s[(nt * 8 + g4) * LDP + kt * 8 + t4 + 4]);
                mma8(of[0][nt], a[0], b0, b1);
                mma8(of[1][nt], a[1], b0, b1);
            }
        }
        __syncwarp();   // done with p_s before next iteration overwrites
    }

    // ---- finalize: reduce l over quad, divide, store O [c][token] ----
    float inv[2][2];
    #pragma unroll
    for (int mt = 0; mt < 2; mt++)
        #pragma unroll
        for (int h = 0; h < 2; h++) {
            float l = lrun[mt][h];
            l += __shfl_xor_sync(0xffffffffu, l, 1);
            l += __shfl_xor_sync(0xffffffffu, l, 2);
            inv[mt][h] = 1.f / l;
        }

    float* ogb = g_o + ((size_t)bb * CC + hh * 64) * HWSZ + i0;
    #pragma unroll
    for (int mt = 0; mt < 2; mt++) {
        int tok0 = wrow + mt * 16 + g4;
        #pragma unroll
        for (int nt = 0; nt < 8; nt++) {
            int ch = nt * 8 + 2 * t4;
            ogb[(size_t)ch * HWSZ + tok0]           = of[mt][nt][0] * inv[mt][0];
            ogb[(size_t)(ch + 1) * HWSZ + tok0]     = of[mt][nt][1] * inv[mt][0];
            ogb[(size_t)ch * HWSZ + tok0 + 8]       = of[mt][nt][2] * inv[mt][1];
            ogb[(size_t)(ch + 1) * HWSZ + tok0 + 8] = of[mt][nt][3] * inv[mt][1];
        }
    }
}

// ============================================================
extern "C" void kernel_launch(void* const* d_in, const int* in_sizes, int n_in,
                              void* d_out, int out_size) {
    const float* x      = (const float*)d_in[0];
    const float* norm_w = (const float*)d_in[1];
    const float* norm_b = (const float*)d_in[2];
    const float* qkv_w  = (const float*)d_in[3];
    const float* qkv_b  = (const float*)d_in[4];
    const float* proj_w = (const float*)d_in[5];
    const float* proj_b = (const float*)d_in[6];
    float* out = (float*)d_out;

    void *ph, *pqkv, *po;
    cudaGetSymbolAddress(&ph,   g_h);
    cudaGetSymbolAddress(&pqkv, g_qkv);
    cudaGetSymbolAddress(&po,   g_o);

    cudaFuncSetAttribute(attn_mma_kernel,
                         cudaFuncAttributeMaxDynamicSharedMemorySize, ATTN_SMEM_BYTES);

    groupnorm_kernel<<<BATCH * NGROUPS, 256>>>(x, norm_w, norm_b);

    gemm_kernel<768, true><<<dim3(HWSZ / 64, 768 / 128, BATCH), 256>>>(
        qkv_w, (const float*)ph, qkv_b, nullptr, (float*)pqkv);

    attn_mma_kernel<<<dim3(HWSZ / 128, NBH), 128, ATTN_SMEM_BYTES>>>();

    gemm_kernel<256, false><<<dim3(HWSZ / 64, 256 / 128, BATCH), 256>>>(
        proj_w, (const float*)po, proj_b, x, out);
}

// round 5
// speedup vs baseline: 3.8907x; 1.3251x over previous
#include <cuda_runtime.h>
#include <math.h>
#include <stdint.h>

#define CC 256
#define HWSZ 4096
#define BATCH 4
#define NHEAD 4
#define NGROUPS 8
#define NBH 16

// -------- scratch (device globals; no allocations allowed) --------
__device__ float g_h  [(size_t)BATCH * CC * HWSZ];        // normalized input
__device__ float g_qkv[(size_t)BATCH * 3 * CC * HWSZ];    // v lives in last third: [b][512 + h*64 + c][token]
__device__ float g_qt [(size_t)NBH * HWSZ * 64];          // q: [bh][token][c], *0.125*log2e, tf32-rounded
__device__ float g_kt [(size_t)NBH * HWSZ * 64];          // k: [bh][token][c], tf32-rounded
__device__ float g_o  [(size_t)BATCH * CC * HWSZ];        // attention out [b][c][token]

// ============================================================
// helpers (sm_80-baseline PTX only — no 'a'-suffix features!)
// ============================================================
__device__ __forceinline__ uint32_t smem_u32(const void* p) {
    uint32_t a;
    asm("{ .reg .u64 t; cvta.to.shared.u64 t, %1; cvt.u32.u64 %0, t; }" : "=r"(a) : "l"(p));
    return a;
}
__device__ __forceinline__ float tf32r(float x) {
    uint32_t u;
    asm("cvt.rna.tf32.f32 %0, %1;" : "=r"(u) : "f"(x));
    return __uint_as_float(u);
}
__device__ __forceinline__ float ex2f(float x) {
    float r;
    asm("ex2.approx.ftz.f32 %0, %1;" : "=f"(r) : "f"(x));
    return r;
}
__device__ __forceinline__ void cp16(uint32_t dst, const void* src) {
    asm volatile("cp.async.cg.shared.global [%0], [%1], 16;" :: "r"(dst), "l"(src) : "memory");
}
#define CP_COMMIT()  asm volatile("cp.async.commit_group;" ::: "memory")
#define CP_WAIT0()   asm volatile("cp.async.wait_group 0;" ::: "memory")

// m16n8k8 tf32 mma: A row-major (4 regs), B col-major (2 regs), C/D f32 (4 regs)
__device__ __forceinline__ void mma8(float c[4], const float a_[4], uint32_t b0, uint32_t b1) {
    asm volatile("mma.sync.aligned.m16n8k8.row.col.f32.tf32.tf32.f32 "
        "{%0,%1,%2,%3}, {%4,%5,%6,%7}, {%8,%9}, {%0,%1,%2,%3};"
        : "+f"(c[0]), "+f"(c[1]), "+f"(c[2]), "+f"(c[3])
        : "r"(__float_as_uint(a_[0])), "r"(__float_as_uint(a_[1])),
          "r"(__float_as_uint(a_[2])), "r"(__float_as_uint(a_[3])),
          "r"(b0), "r"(b1));
}

// ============================================================
// GroupNorm
// ============================================================
__global__ void groupnorm_kernel(const float* __restrict__ x,
                                 const float* __restrict__ w,
                                 const float* __restrict__ b) {
    const int CH = CC / NGROUPS;
    const int NEL = CH * HWSZ;
    int bg = blockIdx.x;
    int bi = bg / NGROUPS, g = bg % NGROUPS;
    const float* xp = x + (size_t)bi * CC * HWSZ + (size_t)g * CH * HWSZ;
    float* hp = g_h + (size_t)bi * CC * HWSZ + (size_t)g * CH * HWSZ;
    int tid = threadIdx.x;

    float s = 0.f, ss = 0.f;
    for (int i = tid * 4; i < NEL; i += blockDim.x * 4) {
        float4 v = *(const float4*)(xp + i);
        s  += v.x + v.y + v.z + v.w;
        ss += v.x * v.x + v.y * v.y + v.z * v.z + v.w * v.w;
    }
    __shared__ float rs[256], rss[256];
    rs[tid] = s; rss[tid] = ss;
    __syncthreads();
    for (int o = 128; o > 0; o >>= 1) {
        if (tid < o) { rs[tid] += rs[tid + o]; rss[tid] += rss[tid + o]; }
        __syncthreads();
    }
    float mean = rs[0] / (float)NEL;
    float var  = rss[0] / (float)NEL - mean * mean;
    float rstd = rsqrtf(var + 1e-5f);

    for (int i = tid * 4; i < NEL; i += blockDim.x * 4) {
        int c = g * CH + (i >> 12);
        float sc  = rstd * w[c];
        float off = b[c] - mean * sc;
        float4 v = *(const float4*)(xp + i);
        float4 o4;
        o4.x = v.x * sc + off;
        o4.y = v.y * sc + off;
        o4.z = v.z * sc + off;
        o4.w = v.w * sc + off;
        *(float4*)(hp + i) = o4;
    }
}

// ============================================================
// Tensor-core tf32 GEMM: out = A[M,256] @ Bm[b][256,HW] + bias (+resid).
// CTA = 128 chans x 128 tokens, K in 8 double-buffered BK=32 stages.
// 8 warps (4x2): each warp 32 rows x 64 cols.
// QKV mode: q -> g_qt (scaled+rounded), k -> g_kt, v -> g_qkv (rounded).
// ============================================================
#define LDA 36
#define LDB 136
#define GEMM_SMEM_BYTES ((2 * 128 * LDA + 2 * 32 * LDB) * 4)

template<int M_TOTAL, bool QKV_MODE>
__global__ void __launch_bounds__(256, 2) gemm_tc_kernel(
        const float* __restrict__ A,
        const float* __restrict__ Bm,
        const float* __restrict__ bias,
        const float* __restrict__ resid,
        float* __restrict__ out) {
    extern __shared__ float sg[];
    float* a_s = sg;                    // 2 bufs [128][LDA]
    float* b_s = sg + 2 * 128 * LDA;    // 2 bufs [32][LDB]
    const uint32_t a_u = smem_u32(a_s);
    const uint32_t b_u = smem_u32(b_s);

    const int tid = threadIdx.x, lane = tid & 31, wid = tid >> 5;
    const int g4 = lane >> 2, t4 = lane & 3;
    const int wm = wid >> 1, wn = wid & 1;
    const int bb = blockIdx.z;
    const int m0 = blockIdx.y * 128;
    const int n0 = blockIdx.x * 128;
    const float* Bp = Bm + (size_t)bb * 256 * HWSZ;

    float acc[2][8][4];
    #pragma unroll
    for (int mt = 0; mt < 2; mt++)
        #pragma unroll
        for (int nt = 0; nt < 8; nt++)
            #pragma unroll
            for (int i = 0; i < 4; i++) acc[mt][nt][i] = 0.f;

    // prologue: stage 0 into buf 0
    #pragma unroll 4
    for (int e = tid; e < 1024; e += 256) {
        int r = e >> 3, c4 = e & 7;
        cp16(a_u + (r * LDA + c4 * 4) * 4, A + (size_t)(m0 + r) * 256 + c4 * 4);
    }
    #pragma unroll 4
    for (int e = tid; e < 1024; e += 256) {
        int r = e >> 5, c4 = e & 31;
        cp16(b_u + (r * LDB + c4 * 4) * 4, Bp + (size_t)r * HWSZ + n0 + c4 * 4);
    }
    CP_COMMIT();

    for (int j = 0; j < 8; j++) {
        const int buf = j & 1;
        const float* at = a_s + buf * 128 * LDA;
        const float* bt = b_s + buf * 32 * LDB;

        CP_WAIT0();
        __syncthreads();

        if (j < 7) {
            const uint32_t ad = a_u + ((buf ^ 1) * 128 * LDA) * 4;
            const uint32_t bd = b_u + ((buf ^ 1) * 32 * LDB) * 4;
            const int k0 = (j + 1) * 32;
            #pragma unroll 4
            for (int e = tid; e < 1024; e += 256) {
                int r = e >> 3, c4 = e & 7;
                cp16(ad + (r * LDA + c4 * 4) * 4, A + (size_t)(m0 + r) * 256 + k0 + c4 * 4);
            }
            #pragma unroll 4
            for (int e = tid; e < 1024; e += 256) {
                int r = e >> 5, c4 = e & 31;
                cp16(bd + (r * LDB + c4 * 4) * 4, Bp + (size_t)(k0 + r) * HWSZ + n0 + c4 * 4);
            }
            CP_COMMIT();
        }

        #pragma unroll
        for (int k8 = 0; k8 < 4; k8++) {
            float af[2][4];
            #pragma unroll
            for (int mt = 0; mt < 2; mt++) {
                const float* ap = at + (wm * 32 + mt * 16 + g4) * LDA + k8 * 8 + t4;
                af[mt][0] = ap[0];
                af[mt][1] = ap[8 * LDA];
                af[mt][2] = ap[4];
                af[mt][3] = ap[8 * LDA + 4];
            }
            const float* bp0 = bt + (k8 * 8 + t4) * LDB + wn * 64 + g4;
            const float* bp1 = bp0 + 4 * LDB;
            #pragma unroll
            for (int nt = 0; nt < 8; nt++) {
                uint32_t b0 = __float_as_uint(bp0[nt * 8]);
                uint32_t b1 = __float_as_uint(bp1[nt * 8]);
                mma8(acc[0][nt], af[0], b0, b1);
                mma8(acc[1][nt], af[1], b0, b1);
            }
        }
        __syncthreads();
    }

    // ---- epilogue ----
    #pragma unroll
    for (int mt = 0; mt < 2; mt++) {
        const int r0 = m0 + wm * 32 + mt * 16 + g4;   // rows r0 and r0+8
        const float bv0 = bias[r0], bv1 = bias[r0 + 8];
        #pragma unroll
        for (int nt = 0; nt < 8; nt++) {
            const int tok = n0 + wn * 64 + nt * 8 + 2 * t4;
            float v0 = acc[mt][nt][0] + bv0;
            float v1 = acc[mt][nt][1] + bv0;
            float v2 = acc[mt][nt][2] + bv1;
            float v3 = acc[mt][nt][3] + bv1;
            if (QKV_MODE) {
                if (m0 < 256) {              // q: scale, round, [bh][token][c]
                    const int bh = bb * NHEAD + (r0 >> 6);
                    const int c0 = r0 & 63;
                    float* gq = g_qt + ((size_t)bh * HWSZ + tok) * 64;
                    gq[c0]          = tf32r(v0 * 0.18033688011112042f);
                    gq[64 + c0]     = tf32r(v1 * 0.18033688011112042f);
                    gq[c0 + 8]      = tf32r(v2 * 0.18033688011112042f);
                    gq[64 + c0 + 8] = tf32r(v3 * 0.18033688011112042f);
                } else if (m0 < 512) {       // k
                    const int bh = bb * NHEAD + ((r0 - 256) >> 6);
                    const int c0 = r0 & 63;
                    float* gk = g_kt + ((size_t)bh * HWSZ + tok) * 64;
                    gk[c0]          = tf32r(v0);
                    gk[64 + c0]     = tf32r(v1);
                    gk[c0 + 8]      = tf32r(v2);
                    gk[64 + c0 + 8] = tf32r(v3);
                } else {                     // v: [ch][token]
                    float* gv = g_qkv + ((size_t)bb * 768 + r0) * HWSZ + tok;
                    *(float2*)gv               = make_float2(tf32r(v0), tf32r(v1));
                    *(float2*)(gv + 8 * HWSZ)  = make_float2(tf32r(v2), tf32r(v3));
                }
            } else {
                const float* rp = resid + ((size_t)bb * 256 + r0) * HWSZ + tok;
                float* op = out + ((size_t)bb * 256 + r0) * HWSZ + tok;
                float2 ra = *(const float2*)rp;
                float2 rb = *(const float2*)(rp + 8 * HWSZ);
                *(float2*)op              = make_float2(v0 + ra.x, v1 + ra.y);
                *(float2*)(op + 8 * HWSZ) = make_float2(v2 + rb.x, v3 + rb.y);
            }
        }
    }
}

// ============================================================
// FlashAttention-2 style tf32 mma.sync attention (unchanged from R4).
// CTA = (bh, 128-query tile); 4 warps x 32 rows; 64 key-tiles of 64.
// ============================================================
#define LDP 68
#define KVSTRIDE (64 * LDP)
#define ATTN_SMEM_BYTES ((4 * KVSTRIDE + 128 * LDP) * 4)

__global__ void __launch_bounds__(128) attn_mma_kernel() {
    extern __shared__ float sm[];
    float* ks_base = sm;
    float* vs_base = sm + 2 * KVSTRIDE;
    float* p_s     = sm + 4 * KVSTRIDE;

    const int tid = threadIdx.x, lane = tid & 31, wid = tid >> 5;
    const int g4 = lane >> 2, t4 = lane & 3;
    const int bh = blockIdx.y;
    const int bb = bh >> 2, hh = bh & 3;
    const int i0 = blockIdx.x * 128;
    const int wrow = wid * 32;

    const float* qg = g_qt + (size_t)bh * HWSZ * 64;
    const float* kg = g_kt + (size_t)bh * HWSZ * 64;
    const float* vg = g_qkv + ((size_t)bb * 768 + 512 + hh * 64) * HWSZ;

    const uint32_t ks_u = smem_u32(ks_base);
    const uint32_t vs_u = smem_u32(vs_base);

    float qf[2][8][4];
    #pragma unroll
    for (int mt = 0; mt < 2; mt++) {
        const float* qr0 = qg + (size_t)(i0 + wrow + mt * 16 + g4) * 64;
        const float* qr1 = qr0 + 8 * 64;
        #pragma unroll
        for (int kt = 0; kt < 8; kt++) {
            qf[mt][kt][0] = qr0[kt * 8 + t4];
            qf[mt][kt][1] = qr1[kt * 8 + t4];
            qf[mt][kt][2] = qr0[kt * 8 + t4 + 4];
            qf[mt][kt][3] = qr1[kt * 8 + t4 + 4];
        }
    }

    float of[2][8][4];
    #pragma unroll
    for (int mt = 0; mt < 2; mt++)
        #pragma unroll
        for (int nt = 0; nt < 8; nt++)
            #pragma unroll
            for (int i = 0; i < 4; i++) of[mt][nt][i] = 0.f;
    float lrun[2][2] = {{0.f, 0.f}, {0.f, 0.f}};

    #pragma unroll 4
    for (int e = tid; e < 1024; e += 128) {
        int r = e >> 4, c = e & 15;
        cp16(ks_u + (r * LDP + c * 4) * 4, kg + (size_t)r * 64 + c * 4);
    }
    #pragma unroll 4
    for (int e = tid; e < 1024; e += 128) {
        int r = e >> 4, c = e & 15;
        cp16(vs_u + (r * LDP + c * 4) * 4, vg + (size_t)r * HWSZ + c * 4);
    }
    CP_COMMIT();

    for (int j = 0; j < 64; j++) {
        const int buf = j & 1;
        const float* kt_s = ks_base + buf * KVSTRIDE;
        const float* vt_s = vs_base + buf * KVSTRIDE;

        CP_WAIT0();
        __syncthreads();

        if (j < 63) {
            const uint32_t kd = ks_u + (buf ^ 1) * KVSTRIDE * 4;
            const uint32_t vd = vs_u + (buf ^ 1) * KVSTRIDE * 4;
            const float* kn = kg + (size_t)(j + 1) * 64 * 64;
            const float* vn = vg + (j + 1) * 64;
            #pragma unroll 4
            for (int e = tid; e < 1024; e += 128) {
                int r = e >> 4, c = e & 15;
                cp16(kd + (r * LDP + c * 4) * 4, kn + (size_t)r * 64 + c * 4);
            }
            #pragma unroll 4
            for (int e = tid; e < 1024; e += 128) {
                int r = e >> 4, c = e & 15;
                cp16(vd + (r * LDP + c * 4) * 4, vn + (size_t)r * HWSZ + c * 4);
            }
            CP_COMMIT();
        }

        float sf[2][8][4];
        #pragma unroll
        for (int mt = 0; mt < 2; mt++)
            #pragma unroll
            for (int nt = 0; nt < 8; nt++)
                #pragma unroll
                for (int i = 0; i < 4; i++) sf[mt][nt][i] = 0.f;

        #pragma unroll
        for (int kt = 0; kt < 8; kt++) {
            #pragma unroll
            for (int nt = 0; nt < 8; nt++) {
                uint32_t b0 = __float_as_uint(kt_s[(nt * 8 + g4) * LDP + kt * 8 + t4]);
                uint32_t b1 = __float_as_uint(kt_s[(nt * 8 + g4) * LDP + kt * 8 + t4 + 4]);
                mma8(sf[0][nt], qf[0][kt], b0, b1);
                mma8(sf[1][nt], qf[1][kt], b0, b1);
            }
        }

        #pragma unroll
        for (int mt = 0; mt < 2; mt++) {
            float* pr0 = p_s + (wrow + mt * 16 + g4) * LDP;
            float* pr1 = pr0 + 8 * LDP;
            #pragma unroll
            for (int nt = 0; nt < 8; nt++) {
                float p0 = tf32r(ex2f(sf[mt][nt][0]));
                float p1 = tf32r(ex2f(sf[mt][nt][1]));
                float p2 = tf32r(ex2f(sf[mt][nt][2]));
                float p3 = tf32r(ex2f(sf[mt][nt][3]));
                lrun[mt][0] += p0 + p1;
                lrun[mt][1] += p2 + p3;
                *(float2*)(pr0 + nt * 8 + 2 * t4) = make_float2(p0, p1);
                *(float2*)(pr1 + nt * 8 + 2 * t4) = make_float2(p2, p3);
            }
        }
        __syncwarp();

        #pragma unroll
        for (int kt = 0; kt < 8; kt++) {
            float a[2][4];
            #pragma unroll
            for (int mt = 0; mt < 2; mt++) {
                const float* pr = p_s + (wrow + mt * 16 + g4) * LDP + kt * 8;
                a[mt][0] = pr[t4];
                a[mt][1] = pr[8 * LDP + t4];
                a[mt][2] = pr[t4 + 4];
                a[mt][3] = pr[8 * LDP + t4 + 4];
            }
            #pragma unroll
            for (int nt = 0; nt < 8; nt++) {
                uint32_t b0 = __float_as_uint(vt_s[(nt * 8 + g4) * LDP + kt * 8 + t4]);
                uint32_t b1 = __float_as_uint(vt_s[(nt * 8 + g4) * LDP + kt * 8 + t4 + 4]);
                mma8(of[0][nt], a[0], b0, b1);
                mma8(of[1][nt], a[1], b0, b1);
            }
        }
        __syncwarp();
    }

    float inv[2][2];
    #pragma unroll
    for (int mt = 0; mt < 2; mt++)
        #pragma unroll
        for (int h = 0; h < 2; h++) {
            float l = lrun[mt][h];
            l += __shfl_xor_sync(0xffffffffu, l, 1);
            l += __shfl_xor_sync(0xffffffffu, l, 2);
            inv[mt][h] = 1.f / l;
        }

    float* ogb = g_o + ((size_t)bb * CC + hh * 64) * HWSZ + i0;
    #pragma unroll
    for (int mt = 0; mt < 2; mt++) {
        int tok0 = wrow + mt * 16 + g4;
        #pragma unroll
        for (int nt = 0; nt < 8; nt++) {
            int ch = nt * 8 + 2 * t4;
            ogb[(size_t)ch * HWSZ + tok0]           = of[mt][nt][0] * inv[mt][0];
            ogb[(size_t)(ch + 1) * HWSZ + tok0]     = of[mt][nt][1] * inv[mt][0];
            ogb[(size_t)ch * HWSZ + tok0 + 8]       = of[mt][nt][2] * inv[mt][1];
            ogb[(size_t)(ch + 1) * HWSZ + tok0 + 8] = of[mt][nt][3] * inv[mt][1];
        }
    }
}

// ============================================================
extern "C" void kernel_launch(void* const* d_in, const int* in_sizes, int n_in,
                              void* d_out, int out_size) {
    const float* x      = (const float*)d_in[0];
    const float* norm_w = (const float*)d_in[1];
    const float* norm_b = (const float*)d_in[2];
    const float* qkv_w  = (const float*)d_in[3];
    const float* qkv_b  = (const float*)d_in[4];
    const float* proj_w = (const float*)d_in[5];
    const float* proj_b = (const float*)d_in[6];
    float* out = (float*)d_out;

    void *ph, *pqkv, *po;
    cudaGetSymbolAddress(&ph,   g_h);
    cudaGetSymbolAddress(&pqkv, g_qkv);
    cudaGetSymbolAddress(&po,   g_o);

    cudaFuncSetAttribute(attn_mma_kernel,
                         cudaFuncAttributeMaxDynamicSharedMemorySize, ATTN_SMEM_BYTES);
    cudaFuncSetAttribute(gemm_tc_kernel<768, true>,
                         cudaFuncAttributeMaxDynamicSharedMemorySize, GEMM_SMEM_BYTES);
    cudaFuncSetAttribute(gemm_tc_kernel<256, false>,
                         cudaFuncAttributeMaxDynamicSharedMemorySize, GEMM_SMEM_BYTES);

    groupnorm_kernel<<<BATCH * NGROUPS, 256>>>(x, norm_w, norm_b);

    gemm_tc_kernel<768, true><<<dim3(HWSZ / 128, 768 / 128, BATCH), 256, GEMM_SMEM_BYTES>>>(
        qkv_w, (const float*)ph, qkv_b, nullptr, (float*)pqkv);

    attn_mma_kernel<<<dim3(HWSZ / 128, NBH), 128, ATTN_SMEM_BYTES>>>();

    gemm_tc_kernel<256, false><<<dim3(HWSZ / 128, 256 / 128, BATCH), 256, GEMM_SMEM_BYTES>>>(
        proj_w, (const float*)po, proj_b, x, out);
}

// round 6
// speedup vs baseline: 6.5345x; 1.6795x over previous
#include <cuda_runtime.h>
#include <cuda_fp16.h>
#include <math.h>
#include <stdint.h>

#define CC 256
#define HWSZ 4096
#define BATCH 4
#define NHEAD 4
#define NGROUPS 8
#define NBH 16

// -------- scratch (device globals; no allocations allowed) --------
__device__ float  g_h [(size_t)BATCH * CC * HWSZ];       // normalized input
__device__ float  g_o [(size_t)BATCH * CC * HWSZ];       // attention out [b][c][token] fp32
__device__ __half g_qh[(size_t)NBH * HWSZ * 64];         // q: [bh][token][c] half, *0.125*log2e
__device__ __half g_kh[(size_t)NBH * HWSZ * 64];         // k: [bh][token][c] half
__device__ __half g_vh[(size_t)NBH * 64 * HWSZ];         // v: [bh][c][token] half

// ============================================================
// helpers (sm_80-baseline PTX only)
// ============================================================
__device__ __forceinline__ uint32_t smem_u32(const void* p) {
    uint32_t a;
    asm("{ .reg .u64 t; cvta.to.shared.u64 t, %1; cvt.u32.u64 %0, t; }" : "=r"(a) : "l"(p));
    return a;
}
__device__ __forceinline__ float ex2f(float x) {
    float r;
    asm("ex2.approx.ftz.f32 %0, %1;" : "=f"(r) : "f"(x));
    return r;
}
__device__ __forceinline__ uint32_t pack_h2(float lo, float hi) {  // {lo, hi} packed halves
    uint32_t d;
    asm("cvt.rn.f16x2.f32 %0, %1, %2;" : "=r"(d) : "f"(hi), "f"(lo));
    return d;
}
__device__ __forceinline__ void cp16(uint32_t dst, const void* src) {
    asm volatile("cp.async.cg.shared.global [%0], [%1], 16;" :: "r"(dst), "l"(src) : "memory");
}
#define CP_COMMIT()  asm volatile("cp.async.commit_group;" ::: "memory")
#define CP_WAIT0()   asm volatile("cp.async.wait_group 0;" ::: "memory")

// tf32 m16n8k8 (GEMMs)
__device__ __forceinline__ void mma8(float c[4], const float a_[4], uint32_t b0, uint32_t b1) {
    asm volatile("mma.sync.aligned.m16n8k8.row.col.f32.tf32.tf32.f32 "
        "{%0,%1,%2,%3}, {%4,%5,%6,%7}, {%8,%9}, {%0,%1,%2,%3};"
        : "+f"(c[0]), "+f"(c[1]), "+f"(c[2]), "+f"(c[3])
        : "r"(__float_as_uint(a_[0])), "r"(__float_as_uint(a_[1])),
          "r"(__float_as_uint(a_[2])), "r"(__float_as_uint(a_[3])),
          "r"(b0), "r"(b1));
}
// fp16 m16n8k16, fp32 accum (attention)
__device__ __forceinline__ void mma16(float c[4], const uint32_t a_[4], uint32_t b0, uint32_t b1) {
    asm volatile("mma.sync.aligned.m16n8k16.row.col.f32.f16.f16.f32 "
        "{%0,%1,%2,%3}, {%4,%5,%6,%7}, {%8,%9}, {%0,%1,%2,%3};"
        : "+f"(c[0]), "+f"(c[1]), "+f"(c[2]), "+f"(c[3])
        : "r"(a_[0]), "r"(a_[1]), "r"(a_[2]), "r"(a_[3]),
          "r"(b0), "r"(b1));
}

// ============================================================
// GroupNorm
// ============================================================
__global__ void groupnorm_kernel(const float* __restrict__ x,
                                 const float* __restrict__ w,
                                 const float* __restrict__ b) {
    const int CH = CC / NGROUPS;
    const int NEL = CH * HWSZ;
    int bg = blockIdx.x;
    int bi = bg / NGROUPS, g = bg % NGROUPS;
    const float* xp = x + (size_t)bi * CC * HWSZ + (size_t)g * CH * HWSZ;
    float* hp = g_h + (size_t)bi * CC * HWSZ + (size_t)g * CH * HWSZ;
    int tid = threadIdx.x;

    float s = 0.f, ss = 0.f;
    for (int i = tid * 4; i < NEL; i += blockDim.x * 4) {
        float4 v = *(const float4*)(xp + i);
        s  += v.x + v.y + v.z + v.w;
        ss += v.x * v.x + v.y * v.y + v.z * v.z + v.w * v.w;
    }
    __shared__ float rs[256], rss[256];
    rs[tid] = s; rss[tid] = ss;
    __syncthreads();
    for (int o = 128; o > 0; o >>= 1) {
        if (tid < o) { rs[tid] += rs[tid + o]; rss[tid] += rss[tid + o]; }
        __syncthreads();
    }
    float mean = rs[0] / (float)NEL;
    float var  = rss[0] / (float)NEL - mean * mean;
    float rstd = rsqrtf(var + 1e-5f);

    for (int i = tid * 4; i < NEL; i += blockDim.x * 4) {
        int c = g * CH + (i >> 12);
        float sc  = rstd * w[c];
        float off = b[c] - mean * sc;
        float4 v = *(const float4*)(xp + i);
        float4 o4;
        o4.x = v.x * sc + off;
        o4.y = v.y * sc + off;
        o4.z = v.z * sc + off;
        o4.w = v.w * sc + off;
        *(float4*)(hp + i) = o4;
    }
}

// ============================================================
// Tensor-core tf32 GEMM (unchanged structure).
// QKV mode: epilogue emits fp16 q (scaled) / k / v into g_qh/g_kh/g_vh.
// ============================================================
#define LDA 36
#define LDB 136
#define GEMM_SMEM_BYTES ((2 * 128 * LDA + 2 * 32 * LDB) * 4)
#define QSCALE 0.18033688011112042f

template<int M_TOTAL, bool QKV_MODE>
__global__ void __launch_bounds__(256, 2) gemm_tc_kernel(
        const float* __restrict__ A,
        const float* __restrict__ Bm,
        const float* __restrict__ bias,
        const float* __restrict__ resid,
        float* __restrict__ out) {
    extern __shared__ float sg[];
    float* a_s = sg;
    float* b_s = sg + 2 * 128 * LDA;
    const uint32_t a_u = smem_u32(a_s);
    const uint32_t b_u = smem_u32(b_s);

    const int tid = threadIdx.x, lane = tid & 31, wid = tid >> 5;
    const int g4 = lane >> 2, t4 = lane & 3;
    const int wm = wid >> 1, wn = wid & 1;
    const int bb = blockIdx.z;
    const int m0 = blockIdx.y * 128;
    const int n0 = blockIdx.x * 128;
    const float* Bp = Bm + (size_t)bb * 256 * HWSZ;

    float acc[2][8][4];
    #pragma unroll
    for (int mt = 0; mt < 2; mt++)
        #pragma unroll
        for (int nt = 0; nt < 8; nt++)
            #pragma unroll
            for (int i = 0; i < 4; i++) acc[mt][nt][i] = 0.f;

    #pragma unroll 4
    for (int e = tid; e < 1024; e += 256) {
        int r = e >> 3, c4 = e & 7;
        cp16(a_u + (r * LDA + c4 * 4) * 4, A + (size_t)(m0 + r) * 256 + c4 * 4);
    }
    #pragma unroll 4
    for (int e = tid; e < 1024; e += 256) {
        int r = e >> 5, c4 = e & 31;
        cp16(b_u + (r * LDB + c4 * 4) * 4, Bp + (size_t)r * HWSZ + n0 + c4 * 4);
    }
    CP_COMMIT();

    for (int j = 0; j < 8; j++) {
        const int buf = j & 1;
        const float* at = a_s + buf * 128 * LDA;
        const float* bt = b_s + buf * 32 * LDB;

        CP_WAIT0();
        __syncthreads();

        if (j < 7) {
            const uint32_t ad = a_u + ((buf ^ 1) * 128 * LDA) * 4;
            const uint32_t bd = b_u + ((buf ^ 1) * 32 * LDB) * 4;
            const int k0 = (j + 1) * 32;
            #pragma unroll 4
            for (int e = tid; e < 1024; e += 256) {
                int r = e >> 3, c4 = e & 7;
                cp16(ad + (r * LDA + c4 * 4) * 4, A + (size_t)(m0 + r) * 256 + k0 + c4 * 4);
            }
            #pragma unroll 4
            for (int e = tid; e < 1024; e += 256) {
                int r = e >> 5, c4 = e & 31;
                cp16(bd + (r * LDB + c4 * 4) * 4, Bp + (size_t)(k0 + r) * HWSZ + n0 + c4 * 4);
            }
            CP_COMMIT();
        }

        #pragma unroll
        for (int k8 = 0; k8 < 4; k8++) {
            float af[2][4];
            #pragma unroll
            for (int mt = 0; mt < 2; mt++) {
                const float* ap = at + (wm * 32 + mt * 16 + g4) * LDA + k8 * 8 + t4;
                af[mt][0] = ap[0];
                af[mt][1] = ap[8 * LDA];
                af[mt][2] = ap[4];
                af[mt][3] = ap[8 * LDA + 4];
            }
            const float* bp0 = bt + (k8 * 8 + t4) * LDB + wn * 64 + g4;
            const float* bp1 = bp0 + 4 * LDB;
            #pragma unroll
            for (int nt = 0; nt < 8; nt++) {
                uint32_t b0 = __float_as_uint(bp0[nt * 8]);
                uint32_t b1 = __float_as_uint(bp1[nt * 8]);
                mma8(acc[0][nt], af[0], b0, b1);
                mma8(acc[1][nt], af[1], b0, b1);
            }
        }
        __syncthreads();
    }

    // ---- epilogue ----
    #pragma unroll
    for (int mt = 0; mt < 2; mt++) {
        const int r0 = m0 + wm * 32 + mt * 16 + g4;
        const float bv0 = bias[r0], bv1 = bias[r0 + 8];
        #pragma unroll
        for (int nt = 0; nt < 8; nt++) {
            const int tok = n0 + wn * 64 + nt * 8 + 2 * t4;
            float v0 = acc[mt][nt][0] + bv0;
            float v1 = acc[mt][nt][1] + bv0;
            float v2 = acc[mt][nt][2] + bv1;
            float v3 = acc[mt][nt][3] + bv1;
            if (QKV_MODE) {
                if (r0 < 256) {              // q -> half, scaled, [bh][token][c]
                    const int bh = bb * NHEAD + (r0 >> 6);
                    const int c0 = r0 & 63;
                    __half* gq = g_qh + ((size_t)bh * HWSZ + tok) * 64;
                    gq[c0]          = __float2half_rn(v0 * QSCALE);
                    gq[64 + c0]     = __float2half_rn(v1 * QSCALE);
                    gq[c0 + 8]      = __float2half_rn(v2 * QSCALE);
                    gq[64 + c0 + 8] = __float2half_rn(v3 * QSCALE);
                } else if (r0 < 512) {       // k -> half
                    const int bh = bb * NHEAD + ((r0 - 256) >> 6);
                    const int c0 = r0 & 63;
                    __half* gk = g_kh + ((size_t)bh * HWSZ + tok) * 64;
                    gk[c0]          = __float2half_rn(v0);
                    gk[64 + c0]     = __float2half_rn(v1);
                    gk[c0 + 8]      = __float2half_rn(v2);
                    gk[64 + c0 + 8] = __float2half_rn(v3);
                } else {                     // v -> half, [bh][c][token]
                    const int cl = r0 - 512;
                    const int bh = bb * NHEAD + (cl >> 6);
                    const int ch = cl & 63;
                    __half* gv = g_vh + ((size_t)bh * 64 + ch) * HWSZ + tok;
                    *(__half2*)gv              = __floats2half2_rn(v0, v1);
                    *(__half2*)(gv + 8 * HWSZ) = __floats2half2_rn(v2, v3);
                }
            } else {
                const float* rp = resid + ((size_t)bb * 256 + r0) * HWSZ + tok;
                float* op = out + ((size_t)bb * 256 + r0) * HWSZ + tok;
                float2 ra = *(const float2*)rp;
                float2 rb = *(const float2*)(rp + 8 * HWSZ);
                *(float2*)op              = make_float2(v0 + ra.x, v1 + ra.y);
                *(float2*)(op + 8 * HWSZ) = make_float2(v2 + rb.x, v3 + rb.y);
            }
        }
    }
}

// ============================================================
// fp16 m16n8k16 flash attention, FA2-style (P stays in registers).
// CTA = (bh, 128-query tile); 4 warps x 32 rows; 64 key-tiles of 64.
// smem: K[2][64][72h] + V[2][64][72h] = 36864 B. No P buffer.
// ============================================================
#define LDH 72                      // halfs per smem row (36 words: 4g4+t4 conflict-free)
#define LDW 36
#define KVW (64 * LDW)              // words per tile buffer
#define ATTN_SMEM_BYTES (4 * KVW * 4)

__global__ void __launch_bounds__(128) attn_mma_kernel() {
    extern __shared__ uint32_t smw[];
    uint32_t* ks_base = smw;                 // 2 bufs [64 tok][36 words]
    uint32_t* vs_base = smw + 2 * KVW;       // 2 bufs [64 chan][36 words]

    const int tid = threadIdx.x, lane = tid & 31, wid = tid >> 5;
    const int g4 = lane >> 2, t4 = lane & 3;
    const int bh = blockIdx.y;
    const int bb = bh >> 2, hh = bh & 3;
    const int i0 = blockIdx.x * 128;
    const int wrow = wid * 32;

    const __half* qg = g_qh + (size_t)bh * HWSZ * 64;
    const __half* kg = g_kh + (size_t)bh * HWSZ * 64;
    const __half* vg = g_vh + (size_t)bh * 64 * HWSZ;

    const uint32_t ks_u = smem_u32(ks_base);
    const uint32_t vs_u = smem_u32(vs_base);

    // ---- Q fragments (half2) in registers for the whole kernel ----
    uint32_t qf[2][4][4];
    #pragma unroll
    for (int mt = 0; mt < 2; mt++) {
        const __half* qr0 = qg + (size_t)(i0 + wrow + mt * 16 + g4) * 64;
        const __half* qr1 = qr0 + 8 * 64;
        #pragma unroll
        for (int kt = 0; kt < 4; kt++) {
            qf[mt][kt][0] = *(const uint32_t*)(qr0 + kt * 16 + 2 * t4);
            qf[mt][kt][1] = *(const uint32_t*)(qr1 + kt * 16 + 2 * t4);
            qf[mt][kt][2] = *(const uint32_t*)(qr0 + kt * 16 + 2 * t4 + 8);
            qf[mt][kt][3] = *(const uint32_t*)(qr1 + kt * 16 + 2 * t4 + 8);
        }
    }

    float of[2][8][4];
    #pragma unroll
    for (int mt = 0; mt < 2; mt++)
        #pragma unroll
        for (int nt = 0; nt < 8; nt++)
            #pragma unroll
            for (int i = 0; i < 4; i++) of[mt][nt][i] = 0.f;
    float lrun[2][2] = {{0.f, 0.f}, {0.f, 0.f}};

    // ---- prologue: tile 0 into buf 0 (K: 512 cp16, V: 512 cp16) ----
    #pragma unroll 4
    for (int e = tid; e < 512; e += 128) {
        int r = e >> 3, c = e & 7;
        cp16(ks_u + r * (LDH * 2) + c * 16, kg + (size_t)r * 64 + c * 8);
    }
    #pragma unroll 4
    for (int e = tid; e < 512; e += 128) {
        int r = e >> 3, c = e & 7;
        cp16(vs_u + r * (LDH * 2) + c * 16, vg + (size_t)r * HWSZ + c * 8);
    }
    CP_COMMIT();

    for (int j = 0; j < 64; j++) {
        const int buf = j & 1;
        const uint32_t* kt_s = ks_base + buf * KVW;
        const uint32_t* vt_s = vs_base + buf * KVW;

        CP_WAIT0();
        __syncthreads();

        if (j < 63) {
            const uint32_t kd = ks_u + (buf ^ 1) * KVW * 4;
            const uint32_t vd = vs_u + (buf ^ 1) * KVW * 4;
            const __half* kn = kg + (size_t)(j + 1) * 64 * 64;
            const __half* vn = vg + (j + 1) * 64;
            #pragma unroll 4
            for (int e = tid; e < 512; e += 128) {
                int r = e >> 3, c = e & 7;
                cp16(kd + r * (LDH * 2) + c * 16, kn + (size_t)r * 64 + c * 8);
            }
            #pragma unroll 4
            for (int e = tid; e < 512; e += 128) {
                int r = e >> 3, c = e & 7;
                cp16(vd + r * (LDH * 2) + c * 16, vn + (size_t)r * HWSZ + c * 8);
            }
            CP_COMMIT();
        }

        // ---- S = Q @ K^T  (per warp: 32 rows x 64 keys) ----
        float sf[2][8][4];
        #pragma unroll
        for (int mt = 0; mt < 2; mt++)
            #pragma unroll
            for (int nt = 0; nt < 8; nt++)
                #pragma unroll
                for (int i = 0; i < 4; i++) sf[mt][nt][i] = 0.f;

        #pragma unroll
        for (int kt = 0; kt < 4; kt++) {
            #pragma unroll
            for (int nt = 0; nt < 8; nt++) {
                uint32_t b0 = kt_s[(nt * 8 + g4) * LDW + kt * 8 + t4];
                uint32_t b1 = kt_s[(nt * 8 + g4) * LDW + kt * 8 + t4 + 4];
                mma16(sf[0][nt], qf[0][kt], b0, b1);
                mma16(sf[1][nt], qf[1][kt], b0, b1);
            }
        }

        // ---- softmax (max-free): P = exp2(S); pack straight into PV A-frags ----
        uint32_t pa[2][4][4];
        #pragma unroll
        for (int mt = 0; mt < 2; mt++) {
            #pragma unroll
            for (int nt = 0; nt < 8; nt++) {
                float p0 = ex2f(sf[mt][nt][0]);
                float p1 = ex2f(sf[mt][nt][1]);
                float p2 = ex2f(sf[mt][nt][2]);
                float p3 = ex2f(sf[mt][nt][3]);
                lrun[mt][0] += p0 + p1;
                lrun[mt][1] += p2 + p3;
                pa[mt][nt >> 1][(nt & 1) * 2]     = pack_h2(p0, p1);
                pa[mt][nt >> 1][(nt & 1) * 2 + 1] = pack_h2(p2, p3);
            }
        }

        // ---- O += P @ V^T ----
        #pragma unroll
        for (int kt = 0; kt < 4; kt++) {
            #pragma unroll
            for (int nt = 0; nt < 8; nt++) {
                uint32_t b0 = vt_s[(nt * 8 + g4) * LDW + kt * 8 + t4];
                uint32_t b1 = vt_s[(nt * 8 + g4) * LDW + kt * 8 + t4 + 4];
                mma16(of[0][nt], pa[0][kt], b0, b1);
                mma16(of[1][nt], pa[1][kt], b0, b1);
            }
        }
    }

    // ---- finalize: reduce l over quad, divide, store O [c][token] fp32 ----
    float inv[2][2];
    #pragma unroll
    for (int mt = 0; mt < 2; mt++)
        #pragma unroll
        for (int h = 0; h < 2; h++) {
            float l = lrun[mt][h];
            l += __shfl_xor_sync(0xffffffffu, l, 1);
            l += __shfl_xor_sync(0xffffffffu, l, 2);
            inv[mt][h] = 1.f / l;
        }

    float* ogb = g_o + ((size_t)bb * CC + hh * 64) * HWSZ + i0;
    #pragma unroll
    for (int mt = 0; mt < 2; mt++) {
        int tok0 = wrow + mt * 16 + g4;
        #pragma unroll
        for (int nt = 0; nt < 8; nt++) {
            int ch = nt * 8 + 2 * t4;
            ogb[(size_t)ch * HWSZ + tok0]           = of[mt][nt][0] * inv[mt][0];
            ogb[(size_t)(ch + 1) * HWSZ + tok0]     = of[mt][nt][1] * inv[mt][0];
            ogb[(size_t)ch * HWSZ + tok0 + 8]       = of[mt][nt][2] * inv[mt][1];
            ogb[(size_t)(ch + 1) * HWSZ + tok0 + 8] = of[mt][nt][3] * inv[mt][1];
        }
    }
}

// ============================================================
extern "C" void kernel_launch(void* const* d_in, const int* in_sizes, int n_in,
                              void* d_out, int out_size) {
    const float* x      = (const float*)d_in[0];
    const float* norm_w = (const float*)d_in[1];
    const float* norm_b = (const float*)d_in[2];
    const float* qkv_w  = (const float*)d_in[3];
    const float* qkv_b  = (const float*)d_in[4];
    const float* proj_w = (const float*)d_in[5];
    const float* proj_b = (const float*)d_in[6];
    float* out = (float*)d_out;

    void *ph, *po;
    cudaGetSymbolAddress(&ph, g_h);
    cudaGetSymbolAddress(&po, g_o);

    cudaFuncSetAttribute(gemm_tc_kernel<768, true>,
                         cudaFuncAttributeMaxDynamicSharedMemorySize, GEMM_SMEM_BYTES);
    cudaFuncSetAttribute(gemm_tc_kernel<256, false>,
                         cudaFuncAttributeMaxDynamicSharedMemorySize, GEMM_SMEM_BYTES);

    groupnorm_kernel<<<BATCH * NGROUPS, 256>>>(x, norm_w, norm_b);

    gemm_tc_kernel<768, true><<<dim3(HWSZ / 128, 768 / 128, BATCH), 256, GEMM_SMEM_BYTES>>>(
        qkv_w, (const float*)ph, qkv_b, nullptr, nullptr);

    attn_mma_kernel<<<dim3(HWSZ / 128, NBH), 128, ATTN_SMEM_BYTES>>>();

    gemm_tc_kernel<256, false><<<dim3(HWSZ / 128, 256 / 128, BATCH), 256, GEMM_SMEM_BYTES>>>(
        proj_w, (const float*)po, proj_b, x, out);
}

// round 7
// speedup vs baseline: 8.0311x; 1.2290x over previous
#include <cuda_runtime.h>
#include <cuda_fp16.h>
#include <math.h>
#include <stdint.h>

#define CC 256
#define HWSZ 4096
#define BATCH 4
#define NHEAD 4
#define NBH 16

// -------- scratch (device globals; no allocations allowed) --------
__device__ __half g_ht [(size_t)BATCH * HWSZ * CC];      // normalized input, [b][tok][c] half
__device__ __half g_oh [(size_t)BATCH * HWSZ * CC];      // attention out, [b][tok][c] half
__device__ __half g_qh [(size_t)NBH * HWSZ * 64];        // q: [bh][tok][c] half, *0.125*log2e
__device__ __half g_kh [(size_t)NBH * HWSZ * 64];        // k: [bh][tok][c] half
__device__ __half g_vh [(size_t)NBH * 64 * HWSZ];        // v: [bh][c][tok] half
__device__ __half g_wqkv[768 * 256];                     // fp16 weights
__device__ __half g_wproj[256 * 256];
__device__ float2 g_part[256];                           // per-slice (sum, sumsq)
__device__ float2 g_stats[32];                           // per (b,group) (mean, rstd)

// ============================================================
// helpers (sm_80-baseline PTX only)
// ============================================================
__device__ __forceinline__ uint32_t smem_u32(const void* p) {
    uint32_t a;
    asm("{ .reg .u64 t; cvta.to.shared.u64 t, %1; cvt.u32.u64 %0, t; }" : "=r"(a) : "l"(p));
    return a;
}
__device__ __forceinline__ float ex2f(float x) {
    float r;
    asm("ex2.approx.ftz.f32 %0, %1;" : "=f"(r) : "f"(x));
    return r;
}
__device__ __forceinline__ uint32_t pack_h2(float lo, float hi) {
    uint32_t d;
    asm("cvt.rn.f16x2.f32 %0, %1, %2;" : "=r"(d) : "f"(hi), "f"(lo));
    return d;
}
__device__ __forceinline__ void cp16(uint32_t dst, const void* src) {
    asm volatile("cp.async.cg.shared.global [%0], [%1], 16;" :: "r"(dst), "l"(src) : "memory");
}
#define CP_COMMIT()  asm volatile("cp.async.commit_group;" ::: "memory")
#define CP_WAIT0()   asm volatile("cp.async.wait_group 0;" ::: "memory")

// fp16 m16n8k16, fp32 accum
__device__ __forceinline__ void mma16(float c[4], const uint32_t a_[4], uint32_t b0, uint32_t b1) {
    asm volatile("mma.sync.aligned.m16n8k16.row.col.f32.f16.f16.f32 "
        "{%0,%1,%2,%3}, {%4,%5,%6,%7}, {%8,%9}, {%0,%1,%2,%3};"
        : "+f"(c[0]), "+f"(c[1]), "+f"(c[2]), "+f"(c[3])
        : "r"(a_[0]), "r"(a_[1]), "r"(a_[2]), "r"(a_[3]),
          "r"(b0), "r"(b1));
}

// ============================================================
// Weight conversion fp32 -> fp16 (once per launch; tiny)
// ============================================================
__global__ void convert_w_kernel(const float* __restrict__ qkv_w,
                                 const float* __restrict__ proj_w) {
    int i = blockIdx.x * 256 + threadIdx.x;
    if (i < 768 * 256) g_wqkv[i] = __float2half_rn(qkv_w[i]);
    else               g_wproj[i - 768 * 256] = __float2half_rn(proj_w[i - 768 * 256]);
}

// ============================================================
// GroupNorm, 3 phases
// ============================================================
__global__ void gn_partial_kernel(const float* __restrict__ x) {
    // block = (bg, slice): bg = blockIdx.x>>3 over 32 (b,group), slice of 16384 floats
    const int bg = blockIdx.x >> 3, sl = blockIdx.x & 7;
    const float* xp = x + (size_t)bg * 131072 + sl * 16384;
    int tid = threadIdx.x;
    float s = 0.f, ss = 0.f;
    #pragma unroll 4
    for (int i = tid * 4; i < 16384; i += 1024) {
        float4 v = *(const float4*)(xp + i);
        s  += v.x + v.y + v.z + v.w;
        ss += v.x * v.x + v.y * v.y + v.z * v.z + v.w * v.w;
    }
    __shared__ float rs[256], rss[256];
    rs[tid] = s; rss[tid] = ss;
    __syncthreads();
    for (int o = 128; o > 0; o >>= 1) {
        if (tid < o) { rs[tid] += rs[tid + o]; rss[tid] += rss[tid + o]; }
        __syncthreads();
    }
    if (tid == 0) g_part[blockIdx.x] = make_float2(rs[0], rss[0]);
}

__global__ void gn_final_kernel() {
    int t = threadIdx.x;   // 32 threads, one per (b,group)
    float s = 0.f, ss = 0.f;
    #pragma unroll
    for (int i = 0; i < 8; i++) { float2 p = g_part[t * 8 + i]; s += p.x; ss += p.y; }
    float mean = s / 131072.f;
    float var  = ss / 131072.f - mean * mean;
    g_stats[t] = make_float2(mean, rsqrtf(var + 1e-5f));
}

// normalize + transpose + fp16: block = (token-tile 128, bg), writes g_ht[b][tok][c]
__global__ void gn_norm_kernel(const float* __restrict__ x,
                               const float* __restrict__ w,
                               const float* __restrict__ b) {
    __shared__ float tile[32][129];
    const int t0 = blockIdx.x * 128;
    const int bg = blockIdx.y;
    const int bb = bg >> 3, gg = bg & 7;
    const int tid = threadIdx.x;

    const float* xp = x + ((size_t)bb * 256 + gg * 32) * HWSZ + t0;
    #pragma unroll 4
    for (int i = tid; i < 1024; i += 256) {
        int row = i >> 5, c4 = i & 31;
        float4 v = *(const float4*)(xp + (size_t)row * HWSZ + c4 * 4);
        tile[row][c4 * 4 + 0] = v.x;
        tile[row][c4 * 4 + 1] = v.y;
        tile[row][c4 * 4 + 2] = v.z;
        tile[row][c4 * 4 + 3] = v.w;
    }
    float2 st = g_stats[bg];
    __syncthreads();

    const int tok = tid >> 1, seg = tid & 1;
    __half hv[16];
    #pragma unroll
    for (int i = 0; i < 16; i++) {
        int cc = seg * 16 + i;
        int c = gg * 32 + cc;
        float sc = st.y * w[c];
        float of = b[c] - st.x * sc;
        hv[i] = __float2half_rn(tile[cc][tok] * sc + of);
    }
    __half* dst = g_ht + ((size_t)bb * HWSZ + t0 + tok) * 256 + gg * 32 + seg * 16;
    *(uint4*)dst       = *(uint4*)hv;
    *(uint4*)(dst + 8) = *(uint4*)(hv + 8);
}

// ============================================================
// fp16 tensor-core GEMM: out = A[M,256] @ h^T  (B given as [tok][c] half).
// CTA = 128 rows x 128 tokens, BK=32, double-buffered. 8 warps (4x2).
// smem rows padded to 40 halves (20 words) -> conflict-free frags.
// ============================================================
#define LDWH 20                       // words per smem row
#define TILEW (128 * LDWH)            // words per buffer
#define GEMM_SMEM_BYTES (4 * TILEW * 4)
#define QSCALE 0.18033688011112042f

template<int M_TOTAL, bool QKV_MODE>
__global__ void __launch_bounds__(256, 2) gemm_h_kernel(
        const __half* __restrict__ A,
        const __half* __restrict__ Bt,     // [b][tok][256] half
        const float* __restrict__ bias,
        const float* __restrict__ resid,
        float* __restrict__ out) {
    extern __shared__ uint32_t sw[];
    uint32_t* a_s = sw;                  // 2 bufs [128 rows][20 words]
    uint32_t* b_s = sw + 2 * TILEW;      // 2 bufs [128 toks][20 words]
    const uint32_t a_u = smem_u32(a_s);
    const uint32_t b_u = smem_u32(b_s);

    const int tid = threadIdx.x, lane = tid & 31, wid = tid >> 5;
    const int g4 = lane >> 2, t4 = lane & 3;
    const int wm = wid >> 1, wn = wid & 1;
    const int bb = blockIdx.z;
    const int m0 = blockIdx.y * 128;
    const int n0 = blockIdx.x * 128;
    const __half* Bp = Bt + (size_t)bb * HWSZ * 256 + (size_t)n0 * 256;

    float acc[2][8][4];
    #pragma unroll
    for (int mt = 0; mt < 2; mt++)
        #pragma unroll
        for (int nt = 0; nt < 8; nt++)
            #pragma unroll
            for (int i = 0; i < 4; i++) acc[mt][nt][i] = 0.f;

    // prologue k0=0
    #pragma unroll 2
    for (int e = tid; e < 512; e += 256) {
        int r = e >> 2, c8 = e & 3;
        cp16(a_u + (r * LDWH + c8 * 4) * 4, A + (size_t)(m0 + r) * 256 + c8 * 8);
    }
    #pragma unroll 2
    for (int e = tid; e < 512; e += 256) {
        int r = e >> 2, c8 = e & 3;
        cp16(b_u + (r * LDWH + c8 * 4) * 4, Bp + (size_t)r * 256 + c8 * 8);
    }
    CP_COMMIT();

    for (int j = 0; j < 8; j++) {
        const int buf = j & 1;
        const uint32_t* at = a_s + buf * TILEW;
        const uint32_t* bt = b_s + buf * TILEW;

        CP_WAIT0();
        __syncthreads();

        if (j < 7) {
            const uint32_t ad = a_u + ((buf ^ 1) * TILEW) * 4;
            const uint32_t bd = b_u + ((buf ^ 1) * TILEW) * 4;
            const int k0 = (j + 1) * 32;
            #pragma unroll 2
            for (int e = tid; e < 512; e += 256) {
                int r = e >> 2, c8 = e & 3;
                cp16(ad + (r * LDWH + c8 * 4) * 4, A + (size_t)(m0 + r) * 256 + k0 + c8 * 8);
            }
            #pragma unroll 2
            for (int e = tid; e < 512; e += 256) {
                int r = e >> 2, c8 = e & 3;
                cp16(bd + (r * LDWH + c8 * 4) * 4, Bp + (size_t)r * 256 + k0 + c8 * 8);
            }
            CP_COMMIT();
        }

        #pragma unroll
        for (int kt = 0; kt < 2; kt++) {
            uint32_t af[2][4];
            #pragma unroll
            for (int mt = 0; mt < 2; mt++) {
                const uint32_t* ap = at + (wm * 32 + mt * 16 + g4) * LDWH + kt * 8 + t4;
                af[mt][0] = ap[0];
                af[mt][1] = ap[8 * LDWH];
                af[mt][2] = ap[4];
                af[mt][3] = ap[8 * LDWH + 4];
            }
            const uint32_t* bp = bt + (wn * 64 + g4) * LDWH + kt * 8 + t4;
            #pragma unroll
            for (int nt = 0; nt < 8; nt++) {
                uint32_t b0 = bp[nt * 8 * LDWH];
                uint32_t b1 = bp[nt * 8 * LDWH + 4];
                mma16(acc[0][nt], af[0], b0, b1);
                mma16(acc[1][nt], af[1], b0, b1);
            }
        }
        __syncthreads();
    }

    // ---- epilogue ----
    #pragma unroll
    for (int mt = 0; mt < 2; mt++) {
        const int r0 = m0 + wm * 32 + mt * 16 + g4;
        const float bv0 = bias[r0], bv1 = bias[r0 + 8];
        #pragma unroll
        for (int nt = 0; nt < 8; nt++) {
            const int tok = n0 + wn * 64 + nt * 8 + 2 * t4;
            float v0 = acc[mt][nt][0] + bv0;
            float v1 = acc[mt][nt][1] + bv0;
            float v2 = acc[mt][nt][2] + bv1;
            float v3 = acc[mt][nt][3] + bv1;
            if (QKV_MODE) {
                if (r0 < 256) {              // q -> half, scaled, [bh][tok][c]
                    const int bh = bb * NHEAD + (r0 >> 6);
                    const int c0 = r0 & 63;
                    __half* gq = g_qh + ((size_t)bh * HWSZ + tok) * 64;
                    gq[c0]          = __float2half_rn(v0 * QSCALE);
                    gq[64 + c0]     = __float2half_rn(v1 * QSCALE);
                    gq[c0 + 8]      = __float2half_rn(v2 * QSCALE);
                    gq[64 + c0 + 8] = __float2half_rn(v3 * QSCALE);
                } else if (r0 < 512) {       // k -> half
                    const int bh = bb * NHEAD + ((r0 - 256) >> 6);
                    const int c0 = r0 & 63;
                    __half* gk = g_kh + ((size_t)bh * HWSZ + tok) * 64;
                    gk[c0]          = __float2half_rn(v0);
                    gk[64 + c0]     = __float2half_rn(v1);
                    gk[c0 + 8]      = __float2half_rn(v2);
                    gk[64 + c0 + 8] = __float2half_rn(v3);
                } else {                     // v -> half, [bh][c][tok]
                    const int cl = r0 - 512;
                    const int bh = bb * NHEAD + (cl >> 6);
                    const int ch = cl & 63;
                    __half* gv = g_vh + ((size_t)bh * 64 + ch) * HWSZ + tok;
                    *(__half2*)gv              = __floats2half2_rn(v0, v1);
                    *(__half2*)(gv + 8 * HWSZ) = __floats2half2_rn(v2, v3);
                }
            } else {
                const float* rp = resid + ((size_t)bb * 256 + r0) * HWSZ + tok;
                float* op = out + ((size_t)bb * 256 + r0) * HWSZ + tok;
                float2 ra = *(const float2*)rp;
                float2 rb = *(const float2*)(rp + 8 * HWSZ);
                *(float2*)op              = make_float2(v0 + ra.x, v1 + ra.y);
                *(float2*)(op + 8 * HWSZ) = make_float2(v2 + rb.x, v3 + rb.y);
            }
        }
    }
}

// ============================================================
// fp16 m16n8k16 flash attention (FA2, P in registers). O -> g_oh [b][tok][c] half.
// ============================================================
#define LDW 36
#define KVW (64 * LDW)
#define ATTN_SMEM_BYTES (4 * KVW * 4)

__global__ void __launch_bounds__(128) attn_mma_kernel() {
    extern __shared__ uint32_t smw[];
    uint32_t* ks_base = smw;
    uint32_t* vs_base = smw + 2 * KVW;

    const int tid = threadIdx.x, lane = tid & 31, wid = tid >> 5;
    const int g4 = lane >> 2, t4 = lane & 3;
    const int bh = blockIdx.y;
    const int bb = bh >> 2, hh = bh & 3;
    const int i0 = blockIdx.x * 128;
    const int wrow = wid * 32;

    const __half* qg = g_qh + (size_t)bh * HWSZ * 64;
    const __half* kg = g_kh + (size_t)bh * HWSZ * 64;
    const __half* vg = g_vh + (size_t)bh * 64 * HWSZ;

    const uint32_t ks_u = smem_u32(ks_base);
    const uint32_t vs_u = smem_u32(vs_base);

    uint32_t qf[2][4][4];
    #pragma unroll
    for (int mt = 0; mt < 2; mt++) {
        const __half* qr0 = qg + (size_t)(i0 + wrow + mt * 16 + g4) * 64;
        const __half* qr1 = qr0 + 8 * 64;
        #pragma unroll
        for (int kt = 0; kt < 4; kt++) {
            qf[mt][kt][0] = *(const uint32_t*)(qr0 + kt * 16 + 2 * t4);
            qf[mt][kt][1] = *(const uint32_t*)(qr1 + kt * 16 + 2 * t4);
            qf[mt][kt][2] = *(const uint32_t*)(qr0 + kt * 16 + 2 * t4 + 8);
            qf[mt][kt][3] = *(const uint32_t*)(qr1 + kt * 16 + 2 * t4 + 8);
        }
    }

    float of[2][8][4];
    #pragma unroll
    for (int mt = 0; mt < 2; mt++)
        #pragma unroll
        for (int nt = 0; nt < 8; nt++)
            #pragma unroll
            for (int i = 0; i < 4; i++) of[mt][nt][i] = 0.f;
    float lrun[2][2] = {{0.f, 0.f}, {0.f, 0.f}};

    #pragma unroll 4
    for (int e = tid; e < 512; e += 128) {
        int r = e >> 3, c = e & 7;
        cp16(ks_u + r * (LDW * 4) + c * 16, kg + (size_t)r * 64 + c * 8);
    }
    #pragma unroll 4
    for (int e = tid; e < 512; e += 128) {
        int r = e >> 3, c = e & 7;
        cp16(vs_u + r * (LDW * 4) + c * 16, vg + (size_t)r * HWSZ + c * 8);
    }
    CP_COMMIT();

    for (int j = 0; j < 64; j++) {
        const int buf = j & 1;
        const uint32_t* kt_s = ks_base + buf * KVW;
        const uint32_t* vt_s = vs_base + buf * KVW;

        CP_WAIT0();
        __syncthreads();

        if (j < 63) {
            const uint32_t kd = ks_u + (buf ^ 1) * KVW * 4;
            const uint32_t vd = vs_u + (buf ^ 1) * KVW * 4;
            const __half* kn = kg + (size_t)(j + 1) * 64 * 64;
            const __half* vn = vg + (j + 1) * 64;
            #pragma unroll 4
            for (int e = tid; e < 512; e += 128) {
                int r = e >> 3, c = e & 7;
                cp16(kd + r * (LDW * 4) + c * 16, kn + (size_t)r * 64 + c * 8);
            }
            #pragma unroll 4
            for (int e = tid; e < 512; e += 128) {
                int r = e >> 3, c = e & 7;
                cp16(vd + r * (LDW * 4) + c * 16, vn + (size_t)r * HWSZ + c * 8);
            }
            CP_COMMIT();
        }

        float sf[2][8][4];
        #pragma unroll
        for (int mt = 0; mt < 2; mt++)
            #pragma unroll
            for (int nt = 0; nt < 8; nt++)
                #pragma unroll
                for (int i = 0; i < 4; i++) sf[mt][nt][i] = 0.f;

        #pragma unroll
        for (int kt = 0; kt < 4; kt++) {
            #pragma unroll
            for (int nt = 0; nt < 8; nt++) {
                uint32_t b0 = kt_s[(nt * 8 + g4) * LDW + kt * 8 + t4];
                uint32_t b1 = kt_s[(nt * 8 + g4) * LDW + kt * 8 + t4 + 4];
                mma16(sf[0][nt], qf[0][kt], b0, b1);
                mma16(sf[1][nt], qf[1][kt], b0, b1);
            }
        }

        uint32_t pa[2][4][4];
        #pragma unroll
        for (int mt = 0; mt < 2; mt++) {
            #pragma unroll
            for (int nt = 0; nt < 8; nt++) {
                float p0 = ex2f(sf[mt][nt][0]);
                float p1 = ex2f(sf[mt][nt][1]);
                float p2 = ex2f(sf[mt][nt][2]);
                float p3 = ex2f(sf[mt][nt][3]);
                lrun[mt][0] += p0 + p1;
                lrun[mt][1] += p2 + p3;
                pa[mt][nt >> 1][(nt & 1) * 2]     = pack_h2(p0, p1);
                pa[mt][nt >> 1][(nt & 1) * 2 + 1] = pack_h2(p2, p3);
            }
        }

        #pragma unroll
        for (int kt = 0; kt < 4; kt++) {
            #pragma unroll
            for (int nt = 0; nt < 8; nt++) {
                uint32_t b0 = vt_s[(nt * 8 + g4) * LDW + kt * 8 + t4];
                uint32_t b1 = vt_s[(nt * 8 + g4) * LDW + kt * 8 + t4 + 4];
                mma16(of[0][nt], pa[0][kt], b0, b1);
                mma16(of[1][nt], pa[1][kt], b0, b1);
            }
        }
    }

    float inv[2][2];
    #pragma unroll
    for (int mt = 0; mt < 2; mt++)
        #pragma unroll
        for (int h = 0; h < 2; h++) {
            float l = lrun[mt][h];
            l += __shfl_xor_sync(0xffffffffu, l, 1);
            l += __shfl_xor_sync(0xffffffffu, l, 2);
            inv[mt][h] = 1.f / l;
        }

    // O -> g_oh[b][tok][256] half (chans hh*64 + ch)
    #pragma unroll
    for (int mt = 0; mt < 2; mt++) {
        int tok = i0 + wrow + mt * 16 + g4;
        __half* d0 = g_oh + ((size_t)bb * HWSZ + tok) * 256 + hh * 64;
        __half* d1 = d0 + 8 * 256;
        #pragma unroll
        for (int nt = 0; nt < 8; nt++) {
            int ch = nt * 8 + 2 * t4;
            *(__half2*)(d0 + ch) = __floats2half2_rn(of[mt][nt][0] * inv[mt][0],
                                                     of[mt][nt][1] * inv[mt][0]);
            *(__half2*)(d1 + ch) = __floats2half2_rn(of[mt][nt][2] * inv[mt][1],
                                                     of[mt][nt][3] * inv[mt][1]);
        }
    }
}

// ============================================================
extern "C" void kernel_launch(void* const* d_in, const int* in_sizes, int n_in,
                              void* d_out, int out_size) {
    const float* x      = (const float*)d_in[0];
    const float* norm_w = (const float*)d_in[1];
    const float* norm_b = (const float*)d_in[2];
    const float* qkv_w  = (const float*)d_in[3];
    const float* qkv_b  = (const float*)d_in[4];
    const float* proj_w = (const float*)d_in[5];
    const float* proj_b = (const float*)d_in[6];
    float* out = (float*)d_out;

    void *pht, *poh, *pwq, *pwp;
    cudaGetSymbolAddress(&pht, g_ht);
    cudaGetSymbolAddress(&poh, g_oh);
    cudaGetSymbolAddress(&pwq, g_wqkv);
    cudaGetSymbolAddress(&pwp, g_wproj);

    cudaFuncSetAttribute(gemm_h_kernel<768, true>,
                         cudaFuncAttributeMaxDynamicSharedMemorySize, GEMM_SMEM_BYTES);
    cudaFuncSetAttribute(gemm_h_kernel<256, false>,
                         cudaFuncAttributeMaxDynamicSharedMemorySize, GEMM_SMEM_BYTES);

    convert_w_kernel<<<1024, 256>>>(qkv_w, proj_w);
    gn_partial_kernel<<<256, 256>>>(x);
    gn_final_kernel<<<1, 32>>>();
    gn_norm_kernel<<<dim3(HWSZ / 128, 32), 256>>>(x, norm_w, norm_b);

    gemm_h_kernel<768, true><<<dim3(HWSZ / 128, 768 / 128, BATCH), 256, GEMM_SMEM_BYTES>>>(
        (const __half*)pwq, (const __half*)pht, qkv_b, nullptr, nullptr);

    attn_mma_kernel<<<dim3(HWSZ / 128, NBH), 128, ATTN_SMEM_BYTES>>>();

    gemm_h_kernel<256, false><<<dim3(HWSZ / 128, 256 / 128, BATCH), 256, GEMM_SMEM_BYTES>>>(
        (const __half*)pwp, (const __half*)poh, proj_b, x, out);
}